// round 14
// baseline (speedup 1.0000x reference)
#include <cuda_runtime.h>
#include <cuda_fp16.h>

#define N_NODES 100000
#define N_EDGES 1000000
#define D_FEAT  64

#define N_TILES   782                 // ceil(N_NODES / 128)
#define GRID_MLP  444                 // 148 SMs x 3 CTAs, persistent
#define MAXB      512                 // per (tile,warp) sub-bucket capacity

// Sub-bucket cursors + entries. g_bcnt zero-init at load; k_gin resets each
// counter after consuming it, so every graph replay sees identical state.
__device__ int g_bcnt[N_TILES * 8];                 // index = v >> 4
__device__ int g_bkt[(size_t)N_TILES * 8 * MAXB];   // entry = (u<<4)|(v&15)

// ---------------------------------------------------------------------------
// k_bin: route both directions of each edge into the destination row-group's
// sub-bucket. 6256 cursors spread across L2 -> cheap atomics.
// ---------------------------------------------------------------------------
__device__ __forceinline__ void push_entry(int u, int v) {
    int idx = v >> 4;                       // tile*8 + warp
    int pos = atomicAdd(&g_bcnt[idx], 1);
    if (pos < MAXB)
        g_bkt[(size_t)idx * MAXB + pos] = (u << 4) | (v & 15);
}

__global__ void k_bin(const int4* __restrict__ ra4, const int4* __restrict__ rb4) {
    int i = blockIdx.x * blockDim.x + threadIdx.x;
    if (i >= N_EDGES / 4) return;
    int4 a4 = __ldg(&ra4[i]);
    int4 b4 = __ldg(&rb4[i]);
    push_entry(b4.x, a4.x); push_entry(a4.x, b4.x);
    push_entry(b4.y, a4.y); push_entry(a4.y, b4.y);
    push_entry(b4.z, a4.z); push_entry(a4.z, b4.z);
    push_entry(b4.w, a4.w); push_entry(a4.w, b4.w);
}

// ---------------------------------------------------------------------------
// k_gin: persistent fused aggregation + FP16 m16n8k16 MLP.
//   out = relu(relu((X[v] + sum_nbr X[u]) @ Wh + bh) @ Wo + bo)
// Warp w exclusively owns Acc rows [16w,16w+16) in every phase:
//   B1: init rows with X (coalesced LDG.128 -> STS, fp32)
//   B2: drain sub-bucket w — whole warp per entry (lane = float2 slice),
//       batch-4 independent loads, non-atomic smem RMW (exclusive rows)
//   MLP: k-permuted fragments + accumulator->layer-2 chaining (round-13)
//   Egress: stage relu(out) in own rows, coalesced STG.128
// No block barrier after weight staging.
// ---------------------------------------------------------------------------
#define ASW 68                                   // Acc row stride (words)
#define GIN_SMEM ((4096 + 128 * ASW) * 4)        // Wp 16KB + Acc 34.8KB

__device__ __forceinline__ unsigned h2(float lo, float hi) {
    __half2 h = __floats2half2_rn(lo, hi);
    return *(unsigned*)&h;
}

__device__ __forceinline__ void mma_f16(float* d, unsigned a0, unsigned a1,
                                        unsigned a2, unsigned a3,
                                        unsigned b0, unsigned b1) {
    asm volatile(
        "mma.sync.aligned.m16n8k16.row.col.f32.f16.f16.f32 "
        "{%0,%1,%2,%3}, {%4,%5,%6,%7}, {%8,%9}, {%0,%1,%2,%3};\n"
        : "+f"(d[0]), "+f"(d[1]), "+f"(d[2]), "+f"(d[3])
        : "r"(a0), "r"(a1), "r"(a2), "r"(a3), "r"(b0), "r"(b1));
}

__global__ __launch_bounds__(256, 3)
void k_gin(const float4* __restrict__ X4, const float2* __restrict__ X2,
           const float* __restrict__ Wh_g, const float* __restrict__ bh,
           const float* __restrict__ Wo_g, const float* __restrict__ bo,
           float4* __restrict__ out4) {
    extern __shared__ unsigned sm[];
    unsigned* Wp = sm;                   // [2][2048] packed fp16 weights
    float*    Acc = (float*)(sm + 4096); // [128][ASW] fp32 accumulator/staging

    const int tid  = threadIdx.x;
    const int lane = tid & 31;
    const int warp = tid >> 5;
    const int g    = lane >> 2;      // 0..7
    const int tg   = lane & 3;       // 0..3

    // ---- Stage weights ONCE (round-13 packing, verified) ----
    #pragma unroll
    for (int l = 0; l < 2; l++) {
        const float* W = l ? Wo_g : Wh_g;
        #pragma unroll
        for (int ii = 0; ii < 2; ii++) {
            int i = tid + ii * 256;
            int ln = i & 31;
            int np = (i >> 5) & 3;
            int s  = i >> 7;
            int tgg = ln & 3, gg = ln >> 2;
            int n0 = 16 * np + gg;
            int n1 = n0 + 8;
            unsigned* dst = &Wp[l * 2048 + i * 4];
            if (l == 0) {
                int r = 16 * tgg + 4 * s;
                dst[0] = h2(__ldg(&W[r * 64 + n0]),       __ldg(&W[(r + 1) * 64 + n0]));
                dst[1] = h2(__ldg(&W[(r + 2) * 64 + n0]), __ldg(&W[(r + 3) * 64 + n0]));
                dst[2] = h2(__ldg(&W[r * 64 + n1]),       __ldg(&W[(r + 1) * 64 + n1]));
                dst[3] = h2(__ldg(&W[(r + 2) * 64 + n1]), __ldg(&W[(r + 3) * 64 + n1]));
            } else {
                int ra = 16 * s + 2 * tgg;
                int rb = ra + 8;
                dst[0] = h2(__ldg(&W[ra * 64 + n0]), __ldg(&W[(ra + 1) * 64 + n0]));
                dst[1] = h2(__ldg(&W[rb * 64 + n0]), __ldg(&W[(rb + 1) * 64 + n0]));
                dst[2] = h2(__ldg(&W[ra * 64 + n1]), __ldg(&W[(ra + 1) * 64 + n1]));
                dst[3] = h2(__ldg(&W[rb * 64 + n1]), __ldg(&W[(rb + 1) * 64 + n1]));
            }
        }
    }
    float bh_lo[8], bh_hi[8], bo_lo[8], bo_hi[8];
    #pragma unroll
    for (int nt = 0; nt < 8; nt++) {
        bh_lo[nt] = __ldg(&bh[nt * 8 + 2 * tg]);
        bh_hi[nt] = __ldg(&bh[nt * 8 + 2 * tg + 1]);
        bo_lo[nt] = __ldg(&bo[nt * 8 + 2 * tg]);
        bo_hi[nt] = __ldg(&bo[nt * 8 + 2 * tg + 1]);
    }
    __syncthreads();   // the ONLY block barrier

    const int lr0 = warp * 16 + g;
    const int lr1 = lr0 + 8;

    // ================= Persistent tile loop (warp free-running) ============
    for (int tile = blockIdx.x; tile < N_TILES; tile += GRID_MLP) {
        const int row0 = tile * 128;

        // ---- B1: init own 16 rows with X (self term), fp32 ----
        #pragma unroll
        for (int i = 0; i < 8; i++) {
            int idx = i * 32 + lane;             // 0..255
            int r  = warp * 16 + (idx >> 4);
            int c4 = idx & 15;
            int grow = row0 + r;
            float4 x = make_float4(0.f, 0.f, 0.f, 0.f);
            if (grow < N_NODES) x = __ldg(&X4[(size_t)grow * 16 + c4]);
            *(float4*)&Acc[r * ASW + c4 * 4] = x;
        }
        __syncwarp();

        // ---- B2: drain own sub-bucket; whole warp per entry ----
        {
            int bidx = tile * 8 + warp;
            int cnt = g_bcnt[bidx];              // uniform -> broadcast
            if (lane == 0) g_bcnt[bidx] = 0;     // reset for next replay
            cnt = min(cnt, MAXB);
            const int* bp = &g_bkt[(size_t)bidx * MAXB];

            int e = 0;
            for (; e + 4 <= cnt; e += 4) {
                int e0 = __ldg(bp + e);
                int e1 = __ldg(bp + e + 1);
                int e2 = __ldg(bp + e + 2);
                int e3 = __ldg(bp + e + 3);
                float2 x0 = __ldg(&X2[(size_t)(e0 >> 4) * 32 + lane]);
                float2 x1 = __ldg(&X2[(size_t)(e1 >> 4) * 32 + lane]);
                float2 x2 = __ldg(&X2[(size_t)(e2 >> 4) * 32 + lane]);
                float2 x3 = __ldg(&X2[(size_t)(e3 >> 4) * 32 + lane]);
                // Non-atomic RMW — rows exclusive to this warp; sequential
                // RMWs keep same-row batches correct (may-alias ordering).
                float2* p0 = (float2*)&Acc[(warp * 16 + (e0 & 15)) * ASW] + lane;
                float2 v0 = *p0; v0.x += x0.x; v0.y += x0.y; *p0 = v0;
                float2* p1 = (float2*)&Acc[(warp * 16 + (e1 & 15)) * ASW] + lane;
                float2 v1 = *p1; v1.x += x1.x; v1.y += x1.y; *p1 = v1;
                float2* p2 = (float2*)&Acc[(warp * 16 + (e2 & 15)) * ASW] + lane;
                float2 v2 = *p2; v2.x += x2.x; v2.y += x2.y; *p2 = v2;
                float2* p3 = (float2*)&Acc[(warp * 16 + (e3 & 15)) * ASW] + lane;
                float2 v3 = *p3; v3.x += x3.x; v3.y += x3.y; *p3 = v3;
            }
            for (; e < cnt; e++) {
                int e0 = __ldg(bp + e);
                float2 x0 = __ldg(&X2[(size_t)(e0 >> 4) * 32 + lane]);
                float2* p0 = (float2*)&Acc[(warp * 16 + (e0 & 15)) * ASW] + lane;
                float2 v0 = *p0; v0.x += x0.x; v0.y += x0.y; *p0 = v0;
            }
        }
        __syncwarp();

        // ---- Pull A fragments (fp32 -> fp16 pairs), own rows ----
        unsigned w0[8], w1[8];           // [m] = phys cols (16tg+2m, +1)
        {
            float f[16];
            *(float4*)&f[0]  = *(float4*)&Acc[lr0 * ASW + 16 * tg];
            *(float4*)&f[4]  = *(float4*)&Acc[lr0 * ASW + 16 * tg + 4];
            *(float4*)&f[8]  = *(float4*)&Acc[lr0 * ASW + 16 * tg + 8];
            *(float4*)&f[12] = *(float4*)&Acc[lr0 * ASW + 16 * tg + 12];
            #pragma unroll
            for (int m = 0; m < 8; m++) w0[m] = h2(f[2 * m], f[2 * m + 1]);
            *(float4*)&f[0]  = *(float4*)&Acc[lr1 * ASW + 16 * tg];
            *(float4*)&f[4]  = *(float4*)&Acc[lr1 * ASW + 16 * tg + 4];
            *(float4*)&f[8]  = *(float4*)&Acc[lr1 * ASW + 16 * tg + 8];
            *(float4*)&f[12] = *(float4*)&Acc[lr1 * ASW + 16 * tg + 12];
            #pragma unroll
            for (int m = 0; m < 8; m++) w1[m] = h2(f[2 * m], f[2 * m + 1]);
        }

        // ================= Layer 1 =================
        float acc[8][4];
        #pragma unroll
        for (int nt = 0; nt < 8; nt++) {
            acc[nt][0] = bh_lo[nt]; acc[nt][1] = bh_hi[nt];
            acc[nt][2] = bh_lo[nt]; acc[nt][3] = bh_hi[nt];
        }
        #pragma unroll
        for (int s = 0; s < 4; s++) {
            unsigned A0 = w0[2 * s],     A1 = w1[2 * s];
            unsigned A2 = w0[2 * s + 1], A3 = w1[2 * s + 1];
            #pragma unroll
            for (int np = 0; np < 4; np++) {
                uint4 b = *(const uint4*)&Wp[((s * 4 + np) * 32 + lane) * 4];
                mma_f16(acc[2 * np],     A0, A1, A2, A3, b.x, b.y);
                mma_f16(acc[2 * np + 1], A0, A1, A2, A3, b.z, b.w);
            }
        }

        // ---- relu + pack: accumulators -> layer-2 A fragments ----
        unsigned ha0[4], ha1[4], ha2[4], ha3[4];
        #pragma unroll
        for (int s = 0; s < 4; s++) {
            ha0[s] = h2(fmaxf(acc[2 * s][0], 0.f),     fmaxf(acc[2 * s][1], 0.f));
            ha1[s] = h2(fmaxf(acc[2 * s][2], 0.f),     fmaxf(acc[2 * s][3], 0.f));
            ha2[s] = h2(fmaxf(acc[2 * s + 1][0], 0.f), fmaxf(acc[2 * s + 1][1], 0.f));
            ha3[s] = h2(fmaxf(acc[2 * s + 1][2], 0.f), fmaxf(acc[2 * s + 1][3], 0.f));
        }

        // ================= Layer 2 =================
        #pragma unroll
        for (int nt = 0; nt < 8; nt++) {
            acc[nt][0] = bo_lo[nt]; acc[nt][1] = bo_hi[nt];
            acc[nt][2] = bo_lo[nt]; acc[nt][3] = bo_hi[nt];
        }
        #pragma unroll
        for (int s = 0; s < 4; s++) {
            #pragma unroll
            for (int np = 0; np < 4; np++) {
                uint4 b = *(const uint4*)&Wp[2048 + ((s * 4 + np) * 32 + lane) * 4];
                mma_f16(acc[2 * np],     ha0[s], ha1[s], ha2[s], ha3[s], b.x, b.y);
                mma_f16(acc[2 * np + 1], ha0[s], ha1[s], ha2[s], ha3[s], b.z, b.w);
            }
        }

        // ---- Egress: relu -> own rows of Acc (fp32), then coalesced STG ----
        __syncwarp();
        #pragma unroll
        for (int nt = 0; nt < 8; nt++) {
            int c = nt * 8 + 2 * tg;
            *(float2*)&Acc[lr0 * ASW + c] = make_float2(
                fmaxf(acc[nt][0], 0.f), fmaxf(acc[nt][1], 0.f));
            *(float2*)&Acc[lr1 * ASW + c] = make_float2(
                fmaxf(acc[nt][2], 0.f), fmaxf(acc[nt][3], 0.f));
        }
        __syncwarp();
        #pragma unroll
        for (int i = 0; i < 8; i++) {
            int idx = i * 32 + lane;
            int r  = warp * 16 + (idx >> 4);
            int c4 = idx & 15;
            int grow = row0 + r;
            if (grow < N_NODES) {
                float4 v = *(float4*)&Acc[r * ASW + c4 * 4];
                out4[(size_t)grow * 16 + c4] = v;
            }
        }
        __syncwarp();   // own-stripe reuse guard before next tile's B1
    }
}

// ---------------------------------------------------------------------------
// Inputs: 0=X, 1=ref_a, 2=ref_b, 3=v_map(unused), 4=v_count(unused),
//         5=W_hidden, 6=b_hidden, 7=W_out, 8=b_out
// ---------------------------------------------------------------------------
extern "C" void kernel_launch(void* const* d_in, const int* in_sizes, int n_in,
                              void* d_out, int out_size) {
    const float* X   = (const float*)d_in[0];
    const int* ref_a = (const int*)d_in[1];
    const int* ref_b = (const int*)d_in[2];
    const float* Wh  = (const float*)d_in[5];
    const float* bh  = (const float*)d_in[6];
    const float* Wo  = (const float*)d_in[7];
    const float* bo  = (const float*)d_in[8];
    float* out = (float*)d_out;

    // 1) bin edge-directions into warp-exclusive sub-buckets
    k_bin<<<(N_EDGES / 4 + 255) / 256, 256>>>((const int4*)ref_a,
                                              (const int4*)ref_b);

    // 2) persistent fused aggregation + MLP (consumes & resets buckets)
    cudaFuncSetAttribute(k_gin, cudaFuncAttributeMaxDynamicSharedMemorySize,
                         GIN_SMEM);
    k_gin<<<GRID_MLP, 256, GIN_SMEM>>>((const float4*)X, (const float2*)X,
                                       Wh, bh, Wo, bo, (float4*)out);
}

// round 15
// speedup vs baseline: 2.2018x; 2.2018x over previous
#include <cuda_runtime.h>
#include <cuda_fp16.h>

#define N_NODES 100000
#define N_EDGES 1000000
#define D_FEAT  64

#define N_TILES   782                 // ceil(N_NODES / 128)
#define GRID_MLP  444                 // 148 SMs x 3 CTAs, persistent

// Neighbor-sum accumulator in FP16 (64 halves per node = 128B rows).
// Zero-initialized at module load; k_mlp re-zeroes its tiles after consuming,
// so every graph replay sees zeros (deterministic).
__device__ __half g_aggh[N_NODES * D_FEAT];

// ---------------------------------------------------------------------------
// Edge scatter: 8 threads per edge, each covers 8 columns (32B fp32 read,
// one 16B red.v4.f16x2 carrying 8 halves) per direction. Halves the RED op
// count vs the fp32 scatter (16M vs 32M lane-REDs) — the measured bottleneck.
// ---------------------------------------------------------------------------
__device__ __forceinline__ void red_v4h(__half* addr, float4 lo, float4 hi) {
    __half2 h0 = __floats2half2_rn(lo.x, lo.y);
    __half2 h1 = __floats2half2_rn(lo.z, lo.w);
    __half2 h2v = __floats2half2_rn(hi.x, hi.y);
    __half2 h3 = __floats2half2_rn(hi.z, hi.w);
    asm volatile("red.global.add.noftz.v4.f16x2 [%0], {%1, %2, %3, %4};"
                 :: "l"(addr),
                    "r"(*(unsigned*)&h0), "r"(*(unsigned*)&h1),
                    "r"(*(unsigned*)&h2v), "r"(*(unsigned*)&h3)
                 : "memory");
}

__global__ void k_scatter(const float4* __restrict__ X4,
                          const int* __restrict__ ref_a,
                          const int* __restrict__ ref_b) {
    unsigned t = blockIdx.x * blockDim.x + threadIdx.x;
    unsigned e = t >> 3;
    unsigned c = t & 7;          // 8 chunks of 8 columns
    if (e >= N_EDGES) return;
    int a = __ldg(&ref_a[e]);
    int b = __ldg(&ref_b[e]);
    float4 xb0 = __ldg(&X4[(size_t)b * 16 + 2 * c]);
    float4 xb1 = __ldg(&X4[(size_t)b * 16 + 2 * c + 1]);
    float4 xa0 = __ldg(&X4[(size_t)a * 16 + 2 * c]);
    float4 xa1 = __ldg(&X4[(size_t)a * 16 + 2 * c + 1]);
    red_v4h(&g_aggh[(size_t)a * 64 + 8 * c], xb0, xb1);
    red_v4h(&g_aggh[(size_t)b * 64 + 8 * c], xa0, xa1);
}

// ---------------------------------------------------------------------------
// Persistent FP16 m16n8k16 register-fragment MLP (fp32 accumulate):
//   out = relu(relu((X+agg) @ Wh + bh) @ Wo + bo)
// Round-13 structure: 444 persistent blocks, weights staged once, warp-private
// Ts stripes, k-permuted fragments + accumulator->layer-2 chaining.
// Ingress now reads the fp16 agg (uint2 = 4 halves) + X fp32 and re-zeroes
// the fp16 agg tile. agg read & zeroed through ONE non-restrict pointer with
// an explicit compiler barrier (round-8 aliasing lesson).
// ---------------------------------------------------------------------------
#define TSW 72                                  // Ts row stride in 32-bit words
#define MLP_SMEM ((4096 + 128 * TSW) * 4)       // Wp 16KB + Ts 36KB = 52.0KB

__device__ __forceinline__ unsigned h2(float lo, float hi) {
    __half2 h = __floats2half2_rn(lo, hi);
    return *(unsigned*)&h;
}

__device__ __forceinline__ void mma_f16(float* d, unsigned a0, unsigned a1,
                                        unsigned a2, unsigned a3,
                                        unsigned b0, unsigned b1) {
    asm volatile(
        "mma.sync.aligned.m16n8k16.row.col.f32.f16.f16.f32 "
        "{%0,%1,%2,%3}, {%4,%5,%6,%7}, {%8,%9}, {%0,%1,%2,%3};\n"
        : "+f"(d[0]), "+f"(d[1]), "+f"(d[2]), "+f"(d[3])
        : "r"(a0), "r"(a1), "r"(a2), "r"(a3), "r"(b0), "r"(b1));
}

__global__ __launch_bounds__(256, 3)
void k_mlp(uint2* aggh2,                        // fp16 agg: read + zeroed (NOT restrict)
           const float4* __restrict__ X4,
           const float* __restrict__ Wh_g, const float* __restrict__ bh,
           const float* __restrict__ Wo_g, const float* __restrict__ bo,
           float4* __restrict__ out4) {
    extern __shared__ unsigned sm[];
    unsigned* Wp = sm;              // [2][2048] packed fp16 weight fragments
    unsigned* Ts = sm + 4096;       // [128][TSW] warp-private staging

    const int tid  = threadIdx.x;
    const int lane = tid & 31;
    const int warp = tid >> 5;
    const int g    = lane >> 2;      // 0..7
    const int tg   = lane & 3;       // 0..3

    // ---- Stage weights ONCE: slot (l, s, np, lane), 4 words per slot ----
    #pragma unroll
    for (int l = 0; l < 2; l++) {
        const float* W = l ? Wo_g : Wh_g;
        #pragma unroll
        for (int ii = 0; ii < 2; ii++) {
            int i = tid + ii * 256;          // 0..511 slots
            int ln = i & 31;
            int np = (i >> 5) & 3;
            int s  = i >> 7;                 // 0..3
            int tgg = ln & 3, gg = ln >> 2;
            int n0 = 16 * np + gg;
            int n1 = n0 + 8;
            unsigned* dst = &Wp[l * 2048 + i * 4];
            if (l == 0) {
                int r = 16 * tgg + 4 * s;
                dst[0] = h2(__ldg(&W[r * 64 + n0]),       __ldg(&W[(r + 1) * 64 + n0]));
                dst[1] = h2(__ldg(&W[(r + 2) * 64 + n0]), __ldg(&W[(r + 3) * 64 + n0]));
                dst[2] = h2(__ldg(&W[r * 64 + n1]),       __ldg(&W[(r + 1) * 64 + n1]));
                dst[3] = h2(__ldg(&W[(r + 2) * 64 + n1]), __ldg(&W[(r + 3) * 64 + n1]));
            } else {
                int ra = 16 * s + 2 * tgg;
                int rb = ra + 8;
                dst[0] = h2(__ldg(&W[ra * 64 + n0]), __ldg(&W[(ra + 1) * 64 + n0]));
                dst[1] = h2(__ldg(&W[rb * 64 + n0]), __ldg(&W[(rb + 1) * 64 + n0]));
                dst[2] = h2(__ldg(&W[ra * 64 + n1]), __ldg(&W[(ra + 1) * 64 + n1]));
                dst[3] = h2(__ldg(&W[rb * 64 + n1]), __ldg(&W[(rb + 1) * 64 + n1]));
            }
        }
    }
    // Bias fragments (constant across tiles).
    float bh_lo[8], bh_hi[8], bo_lo[8], bo_hi[8];
    #pragma unroll
    for (int nt = 0; nt < 8; nt++) {
        bh_lo[nt] = __ldg(&bh[nt * 8 + 2 * tg]);
        bh_hi[nt] = __ldg(&bh[nt * 8 + 2 * tg + 1]);
        bo_lo[nt] = __ldg(&bo[nt * 8 + 2 * tg]);
        bo_hi[nt] = __ldg(&bo[nt * 8 + 2 * tg + 1]);
    }
    __syncthreads();   // the only block barrier

    const int lr0 = warp * 16 + g;
    const int lr1 = lr0 + 8;

    // ================= Persistent tile loop =================
    for (int tile = blockIdx.x; tile < N_TILES; tile += GRID_MLP) {
        const int row0 = tile * 128;

        // ---- Per-warp coalesced ingress: own 16 rows of half2(X + agg) ----
        #pragma unroll
        for (int i = 0; i < 8; i++) {
            int idx = i * 32 + lane;             // 0..255
            int r  = warp * 16 + (idx >> 4);     // local row (warp-private)
            int c4 = idx & 15;                   // 4-col chunk
            int grow = row0 + r;
            uint2 st = make_uint2(0u, 0u);
            if (grow < N_NODES) {
                uint2 ah = aggh2[(size_t)grow * 16 + c4];   // 4 halves
                float4 x = __ldg(&X4[(size_t)grow * 16 + c4]);
                float2 a0 = __half22float2(*(__half2*)&ah.x);
                float2 a1 = __half22float2(*(__half2*)&ah.y);
                st.x = h2(a0.x + x.x, a0.y + x.y);
                st.y = h2(a1.x + x.z, a1.y + x.w);
            }
            *(uint2*)&Ts[r * TSW + c4 * 2] = st;
        }

        // Compiler barrier: agg loads above must materialize before the
        // zeroing stores below (same buffer!).
        asm volatile("" ::: "memory");

        // Re-zero own fp16 agg rows (16 rows x 128B = 128 uint4 per warp).
        {
            const uint4 z4 = make_uint4(0u, 0u, 0u, 0u);
            uint4* aggh4 = (uint4*)aggh2;
            #pragma unroll
            for (int i = 0; i < 4; i++) {
                int idx = i * 32 + lane;          // 0..127
                int r  = warp * 16 + (idx >> 3);
                int c8 = idx & 7;                 // uint4 within row (8/row)
                int grow = row0 + r;
                if (grow < N_NODES)
                    aggh4[(size_t)grow * 8 + c8] = z4;
            }
        }
        __syncwarp();

        // ---- Pull A fragments: words [8tg, 8tg+8) of own two rows ----
        unsigned w0[8], w1[8];       // [m] = phys cols (16tg+2m, 16tg+2m+1)
        *(uint4*)&w0[0] = *(const uint4*)&Ts[lr0 * TSW + 8 * tg];
        *(uint4*)&w0[4] = *(const uint4*)&Ts[lr0 * TSW + 8 * tg + 4];
        *(uint4*)&w1[0] = *(const uint4*)&Ts[lr1 * TSW + 8 * tg];
        *(uint4*)&w1[4] = *(const uint4*)&Ts[lr1 * TSW + 8 * tg + 4];

        // ================= Layer 1 =================
        float acc[8][4];
        #pragma unroll
        for (int nt = 0; nt < 8; nt++) {
            acc[nt][0] = bh_lo[nt]; acc[nt][1] = bh_hi[nt];
            acc[nt][2] = bh_lo[nt]; acc[nt][3] = bh_hi[nt];
        }
        #pragma unroll
        for (int s = 0; s < 4; s++) {
            unsigned A0 = w0[2 * s],     A1 = w1[2 * s];
            unsigned A2 = w0[2 * s + 1], A3 = w1[2 * s + 1];
            #pragma unroll
            for (int np = 0; np < 4; np++) {
                uint4 b = *(const uint4*)&Wp[((s * 4 + np) * 32 + lane) * 4];
                mma_f16(acc[2 * np],     A0, A1, A2, A3, b.x, b.y);
                mma_f16(acc[2 * np + 1], A0, A1, A2, A3, b.z, b.w);
            }
        }

        // ---- relu + pack: accumulators become layer-2 A fragments ----
        unsigned ha0[4], ha1[4], ha2[4], ha3[4];
        #pragma unroll
        for (int s = 0; s < 4; s++) {
            ha0[s] = h2(fmaxf(acc[2 * s][0], 0.f),     fmaxf(acc[2 * s][1], 0.f));
            ha1[s] = h2(fmaxf(acc[2 * s][2], 0.f),     fmaxf(acc[2 * s][3], 0.f));
            ha2[s] = h2(fmaxf(acc[2 * s + 1][0], 0.f), fmaxf(acc[2 * s + 1][1], 0.f));
            ha3[s] = h2(fmaxf(acc[2 * s + 1][2], 0.f), fmaxf(acc[2 * s + 1][3], 0.f));
        }

        // ================= Layer 2 =================
        #pragma unroll
        for (int nt = 0; nt < 8; nt++) {
            acc[nt][0] = bo_lo[nt]; acc[nt][1] = bo_hi[nt];
            acc[nt][2] = bo_lo[nt]; acc[nt][3] = bo_hi[nt];
        }
        #pragma unroll
        for (int s = 0; s < 4; s++) {
            #pragma unroll
            for (int np = 0; np < 4; np++) {
                uint4 b = *(const uint4*)&Wp[2048 + ((s * 4 + np) * 32 + lane) * 4];
                mma_f16(acc[2 * np],     ha0[s], ha1[s], ha2[s], ha3[s], b.x, b.y);
                mma_f16(acc[2 * np + 1], ha0[s], ha1[s], ha2[s], ha3[s], b.z, b.w);
            }
        }

        // ---- Egress: relu -> own warp stripe as fp32 (warp-private) ----
        __syncwarp();
        #pragma unroll
        for (int nt = 0; nt < 8; nt++) {
            int c = nt * 8 + 2 * tg;
            *(uint2*)&Ts[lr0 * TSW + c] = make_uint2(
                __float_as_uint(fmaxf(acc[nt][0], 0.f)),
                __float_as_uint(fmaxf(acc[nt][1], 0.f)));
            *(uint2*)&Ts[lr1 * TSW + c] = make_uint2(
                __float_as_uint(fmaxf(acc[nt][2], 0.f)),
                __float_as_uint(fmaxf(acc[nt][3], 0.f)));
        }
        __syncwarp();

        // ---- Per-warp coalesced STG.128 of own 16 output rows ----
        #pragma unroll
        for (int i = 0; i < 8; i++) {
            int idx = i * 32 + lane;
            int r  = warp * 16 + (idx >> 4);
            int c4 = idx & 15;
            int grow = row0 + r;
            if (grow < N_NODES) {
                uint4 v = *(const uint4*)&Ts[r * TSW + c4 * 4];
                out4[(size_t)grow * 16 + c4] = make_float4(
                    __uint_as_float(v.x), __uint_as_float(v.y),
                    __uint_as_float(v.z), __uint_as_float(v.w));
            }
        }
        __syncwarp();   // stripe reuse guard before next tile's ingress
    }
}

// ---------------------------------------------------------------------------
// Inputs: 0=X, 1=ref_a, 2=ref_b, 3=v_map(unused), 4=v_count(unused),
//         5=W_hidden, 6=b_hidden, 7=W_out, 8=b_out
// ---------------------------------------------------------------------------
extern "C" void kernel_launch(void* const* d_in, const int* in_sizes, int n_in,
                              void* d_out, int out_size) {
    const float* X   = (const float*)d_in[0];
    const int* ref_a = (const int*)d_in[1];
    const int* ref_b = (const int*)d_in[2];
    const float* Wh  = (const float*)d_in[5];
    const float* bh  = (const float*)d_in[6];
    const float* Wo  = (const float*)d_in[7];
    const float* bo  = (const float*)d_in[8];
    float* out = (float*)d_out;

    __half* aggh;
    cudaGetSymbolAddress((void**)&aggh, g_aggh);

    // 1) edge scatter with f16x2 REDs (zero-invariant maintained by k_mlp)
    {
        long long total = (long long)N_EDGES * 8;
        int blocks = (int)((total + 255) / 256);
        k_scatter<<<blocks, 256>>>((const float4*)X, ref_a, ref_b);
    }

    // 2) persistent FP16 register-fragment MLP
    {
        cudaFuncSetAttribute(k_mlp, cudaFuncAttributeMaxDynamicSharedMemorySize,
                             MLP_SMEM);
        k_mlp<<<GRID_MLP, 256, MLP_SMEM>>>((uint2*)aggh, (const float4*)X,
                                           Wh, bh, Wo, bo, (float4*)out);
    }
}

// round 16
// speedup vs baseline: 2.3508x; 1.0677x over previous
#include <cuda_runtime.h>
#include <cuda_fp16.h>

#define N_NODES 100000
#define N_EDGES 1000000
#define D_FEAT  64

#define N_TILES   782                 // ceil(N_NODES / 128)
#define GRID_MLP  444                 // 148 SMs x 3 CTAs, persistent

// g_xh:   fp16 copy of X (read-only source for the scatter).
// g_aggh: fp16 accumulator, pre-seeded with fp16(X) by k_init every call, so
//         after the scatter it holds fp16(X[v] + sum_nbr X[u]). k_init
//         overwrites it each call -> graph-replay deterministic, no zeroing.
__device__ __half g_xh[N_NODES * D_FEAT];
__device__ __half g_aggh[N_NODES * D_FEAT];

// ---------------------------------------------------------------------------
// k_init: X (fp32) -> g_xh AND g_aggh (fp16). 25.6MB read + 2x12.8MB write.
// ---------------------------------------------------------------------------
__global__ void k_init(const float4* __restrict__ X4,
                       uint4* __restrict__ xh4, uint4* __restrict__ aggh4,
                       int n) {
    int i = blockIdx.x * blockDim.x + threadIdx.x;   // n = N_NODES*8 uint4
    if (i >= n) return;
    float4 a = __ldg(&X4[2 * i]);
    float4 b = __ldg(&X4[2 * i + 1]);
    __half2 h0 = __floats2half2_rn(a.x, a.y);
    __half2 h1 = __floats2half2_rn(a.z, a.w);
    __half2 h2v = __floats2half2_rn(b.x, b.y);
    __half2 h3 = __floats2half2_rn(b.z, b.w);
    uint4 v = make_uint4(*(unsigned*)&h0, *(unsigned*)&h1,
                         *(unsigned*)&h2v, *(unsigned*)&h3);
    xh4[i] = v;
    aggh4[i] = v;
}

// ---------------------------------------------------------------------------
// Edge scatter: 8 threads per edge; each thread reads 8 fp16 columns (one
// LDG.128 from g_xh, NO conversion) and issues one red.v4.f16x2 per direction.
// 16M lane-REDs total — at the halved RED-op floor measured in round 15.
// ---------------------------------------------------------------------------
__device__ __forceinline__ void red16(__half* addr, uint4 h) {
    asm volatile("red.global.add.noftz.v4.f16x2 [%0], {%1, %2, %3, %4};"
                 :: "l"(addr), "r"(h.x), "r"(h.y), "r"(h.z), "r"(h.w)
                 : "memory");
}

__global__ void k_scatter(const uint4* __restrict__ Xh4,
                          const int* __restrict__ ref_a,
                          const int* __restrict__ ref_b) {
    unsigned t = blockIdx.x * blockDim.x + threadIdx.x;
    unsigned e = t >> 3;
    unsigned c = t & 7;          // 8 chunks of 8 fp16 columns (16B each)
    if (e >= N_EDGES) return;
    int a = __ldg(&ref_a[e]);
    int b = __ldg(&ref_b[e]);
    uint4 hb = __ldg(&Xh4[(size_t)b * 8 + c]);
    uint4 ha = __ldg(&Xh4[(size_t)a * 8 + c]);
    red16(&g_aggh[(size_t)a * 64 + 8 * c], hb);
    red16(&g_aggh[(size_t)b * 64 + 8 * c], ha);
}

// ---------------------------------------------------------------------------
// Persistent FP16 m16n8k16 register-fragment MLP (fp32 accumulate):
//   out = relu(relu(agg @ Wh + bh) @ Wo + bo),  agg = fp16(X + sum_nbr X)
// Round-13/15 structure, but ingress is now a PURE COPY (agg is already the
// fp16 half2 tile): 4x LDG.128 -> STS.128 per lane. No X read, no zeroing,
// no cvt, no aliasing barrier. Warp-private Ts stripes; k-permuted fragments;
// layer-1 accumulators chain directly into layer 2.
// ---------------------------------------------------------------------------
#define TSW 72                                  // Ts row stride in 32-bit words
#define MLP_SMEM ((4096 + 128 * TSW) * 4)       // Wp 16KB + Ts 36KB = 52.0KB

__device__ __forceinline__ unsigned h2(float lo, float hi) {
    __half2 h = __floats2half2_rn(lo, hi);
    return *(unsigned*)&h;
}

__device__ __forceinline__ void mma_f16(float* d, unsigned a0, unsigned a1,
                                        unsigned a2, unsigned a3,
                                        unsigned b0, unsigned b1) {
    asm volatile(
        "mma.sync.aligned.m16n8k16.row.col.f32.f16.f16.f32 "
        "{%0,%1,%2,%3}, {%4,%5,%6,%7}, {%8,%9}, {%0,%1,%2,%3};\n"
        : "+f"(d[0]), "+f"(d[1]), "+f"(d[2]), "+f"(d[3])
        : "r"(a0), "r"(a1), "r"(a2), "r"(a3), "r"(b0), "r"(b1));
}

__global__ __launch_bounds__(256, 3)
void k_mlp(const uint4* __restrict__ aggh4,
           const float* __restrict__ Wh_g, const float* __restrict__ bh,
           const float* __restrict__ Wo_g, const float* __restrict__ bo,
           float4* __restrict__ out4) {
    extern __shared__ unsigned sm[];
    unsigned* Wp = sm;              // [2][2048] packed fp16 weight fragments
    unsigned* Ts = sm + 4096;       // [128][TSW] warp-private staging

    const int tid  = threadIdx.x;
    const int lane = tid & 31;
    const int warp = tid >> 5;
    const int g    = lane >> 2;      // 0..7
    const int tg   = lane & 3;       // 0..3

    // ---- Stage weights ONCE: slot (l, s, np, lane), 4 words per slot ----
    #pragma unroll
    for (int l = 0; l < 2; l++) {
        const float* W = l ? Wo_g : Wh_g;
        #pragma unroll
        for (int ii = 0; ii < 2; ii++) {
            int i = tid + ii * 256;          // 0..511 slots
            int ln = i & 31;
            int np = (i >> 5) & 3;
            int s  = i >> 7;                 // 0..3
            int tgg = ln & 3, gg = ln >> 2;
            int n0 = 16 * np + gg;
            int n1 = n0 + 8;
            unsigned* dst = &Wp[l * 2048 + i * 4];
            if (l == 0) {
                int r = 16 * tgg + 4 * s;
                dst[0] = h2(__ldg(&W[r * 64 + n0]),       __ldg(&W[(r + 1) * 64 + n0]));
                dst[1] = h2(__ldg(&W[(r + 2) * 64 + n0]), __ldg(&W[(r + 3) * 64 + n0]));
                dst[2] = h2(__ldg(&W[r * 64 + n1]),       __ldg(&W[(r + 1) * 64 + n1]));
                dst[3] = h2(__ldg(&W[(r + 2) * 64 + n1]), __ldg(&W[(r + 3) * 64 + n1]));
            } else {
                int ra = 16 * s + 2 * tgg;
                int rb = ra + 8;
                dst[0] = h2(__ldg(&W[ra * 64 + n0]), __ldg(&W[(ra + 1) * 64 + n0]));
                dst[1] = h2(__ldg(&W[rb * 64 + n0]), __ldg(&W[(rb + 1) * 64 + n0]));
                dst[2] = h2(__ldg(&W[ra * 64 + n1]), __ldg(&W[(ra + 1) * 64 + n1]));
                dst[3] = h2(__ldg(&W[rb * 64 + n1]), __ldg(&W[(rb + 1) * 64 + n1]));
            }
        }
    }
    // Bias fragments (constant across tiles).
    float bh_lo[8], bh_hi[8], bo_lo[8], bo_hi[8];
    #pragma unroll
    for (int nt = 0; nt < 8; nt++) {
        bh_lo[nt] = __ldg(&bh[nt * 8 + 2 * tg]);
        bh_hi[nt] = __ldg(&bh[nt * 8 + 2 * tg + 1]);
        bo_lo[nt] = __ldg(&bo[nt * 8 + 2 * tg]);
        bo_hi[nt] = __ldg(&bo[nt * 8 + 2 * tg + 1]);
    }
    __syncthreads();   // the only block barrier

    const int lr0 = warp * 16 + g;
    const int lr1 = lr0 + 8;

    // ================= Persistent tile loop =================
    for (int tile = blockIdx.x; tile < N_TILES; tile += GRID_MLP) {
        const int row0 = tile * 128;

        // ---- Ingress: pure copy of own 16 fp16 rows (4x LDG.128->STS.128) --
        #pragma unroll
        for (int i = 0; i < 4; i++) {
            int idx = i * 32 + lane;             // 0..127 uint4 in warp tile
            int r  = warp * 16 + (idx >> 3);     // local row (warp-private)
            int c8 = idx & 7;                    // 8-col chunk (uint4)
            int grow = row0 + r;
            uint4 v = make_uint4(0u, 0u, 0u, 0u);
            if (grow < N_NODES) v = __ldg(&aggh4[(size_t)grow * 8 + c8]);
            *(uint4*)&Ts[r * TSW + c8 * 4] = v;
        }
        __syncwarp();

        // ---- Pull A fragments: words [8tg, 8tg+8) of own two rows ----
        unsigned w0[8], w1[8];       // [m] = phys cols (16tg+2m, 16tg+2m+1)
        *(uint4*)&w0[0] = *(const uint4*)&Ts[lr0 * TSW + 8 * tg];
        *(uint4*)&w0[4] = *(const uint4*)&Ts[lr0 * TSW + 8 * tg + 4];
        *(uint4*)&w1[0] = *(const uint4*)&Ts[lr1 * TSW + 8 * tg];
        *(uint4*)&w1[4] = *(const uint4*)&Ts[lr1 * TSW + 8 * tg + 4];

        // ================= Layer 1 =================
        float acc[8][4];
        #pragma unroll
        for (int nt = 0; nt < 8; nt++) {
            acc[nt][0] = bh_lo[nt]; acc[nt][1] = bh_hi[nt];
            acc[nt][2] = bh_lo[nt]; acc[nt][3] = bh_hi[nt];
        }
        #pragma unroll
        for (int s = 0; s < 4; s++) {
            unsigned A0 = w0[2 * s],     A1 = w1[2 * s];
            unsigned A2 = w0[2 * s + 1], A3 = w1[2 * s + 1];
            #pragma unroll
            for (int np = 0; np < 4; np++) {
                uint4 b = *(const uint4*)&Wp[((s * 4 + np) * 32 + lane) * 4];
                mma_f16(acc[2 * np],     A0, A1, A2, A3, b.x, b.y);
                mma_f16(acc[2 * np + 1], A0, A1, A2, A3, b.z, b.w);
            }
        }

        // ---- relu + pack: accumulators become layer-2 A fragments ----
        unsigned ha0[4], ha1[4], ha2[4], ha3[4];
        #pragma unroll
        for (int s = 0; s < 4; s++) {
            ha0[s] = h2(fmaxf(acc[2 * s][0], 0.f),     fmaxf(acc[2 * s][1], 0.f));
            ha1[s] = h2(fmaxf(acc[2 * s][2], 0.f),     fmaxf(acc[2 * s][3], 0.f));
            ha2[s] = h2(fmaxf(acc[2 * s + 1][0], 0.f), fmaxf(acc[2 * s + 1][1], 0.f));
            ha3[s] = h2(fmaxf(acc[2 * s + 1][2], 0.f), fmaxf(acc[2 * s + 1][3], 0.f));
        }

        // ================= Layer 2 =================
        #pragma unroll
        for (int nt = 0; nt < 8; nt++) {
            acc[nt][0] = bo_lo[nt]; acc[nt][1] = bo_hi[nt];
            acc[nt][2] = bo_lo[nt]; acc[nt][3] = bo_hi[nt];
        }
        #pragma unroll
        for (int s = 0; s < 4; s++) {
            #pragma unroll
            for (int np = 0; np < 4; np++) {
                uint4 b = *(const uint4*)&Wp[2048 + ((s * 4 + np) * 32 + lane) * 4];
                mma_f16(acc[2 * np],     ha0[s], ha1[s], ha2[s], ha3[s], b.x, b.y);
                mma_f16(acc[2 * np + 1], ha0[s], ha1[s], ha2[s], ha3[s], b.z, b.w);
            }
        }

        // ---- Egress: relu -> own warp stripe as fp32 (warp-private) ----
        __syncwarp();
        #pragma unroll
        for (int nt = 0; nt < 8; nt++) {
            int c = nt * 8 + 2 * tg;
            *(uint2*)&Ts[lr0 * TSW + c] = make_uint2(
                __float_as_uint(fmaxf(acc[nt][0], 0.f)),
                __float_as_uint(fmaxf(acc[nt][1], 0.f)));
            *(uint2*)&Ts[lr1 * TSW + c] = make_uint2(
                __float_as_uint(fmaxf(acc[nt][2], 0.f)),
                __float_as_uint(fmaxf(acc[nt][3], 0.f)));
        }
        __syncwarp();

        // ---- Per-warp coalesced STG.128 of own 16 output rows ----
        #pragma unroll
        for (int i = 0; i < 8; i++) {
            int idx = i * 32 + lane;
            int r  = warp * 16 + (idx >> 4);
            int c4 = idx & 15;
            int grow = row0 + r;
            if (grow < N_NODES) {
                uint4 v = *(const uint4*)&Ts[r * TSW + c4 * 4];
                out4[(size_t)grow * 16 + c4] = make_float4(
                    __uint_as_float(v.x), __uint_as_float(v.y),
                    __uint_as_float(v.z), __uint_as_float(v.w));
            }
        }
        __syncwarp();   // stripe reuse guard before next tile's ingress
    }
}

// ---------------------------------------------------------------------------
// Inputs: 0=X, 1=ref_a, 2=ref_b, 3=v_map(unused), 4=v_count(unused),
//         5=W_hidden, 6=b_hidden, 7=W_out, 8=b_out
// ---------------------------------------------------------------------------
extern "C" void kernel_launch(void* const* d_in, const int* in_sizes, int n_in,
                              void* d_out, int out_size) {
    const float* X   = (const float*)d_in[0];
    const int* ref_a = (const int*)d_in[1];
    const int* ref_b = (const int*)d_in[2];
    const float* Wh  = (const float*)d_in[5];
    const float* bh  = (const float*)d_in[6];
    const float* Wo  = (const float*)d_in[7];
    const float* bo  = (const float*)d_in[8];
    float* out = (float*)d_out;

    __half* xh;
    cudaGetSymbolAddress((void**)&xh, g_xh);
    __half* aggh;
    cudaGetSymbolAddress((void**)&aggh, g_aggh);

    // 1) fp16 X copy + accumulator pre-seeded with the self term
    {
        int n = N_NODES * D_FEAT / 8;    // 800k uint4
        k_init<<<(n + 255) / 256, 256>>>((const float4*)X, (uint4*)xh,
                                         (uint4*)aggh, n);
    }

    // 2) edge scatter: fp16 reads, f16x2 REDs (no conversion anywhere)
    {
        long long total = (long long)N_EDGES * 8;
        int blocks = (int)((total + 255) / 256);
        k_scatter<<<blocks, 256>>>((const uint4*)xh, ref_a, ref_b);
    }

    // 3) persistent FP16 MLP (pure-copy ingress; no zeroing needed)
    {
        cudaFuncSetAttribute(k_mlp, cudaFuncAttributeMaxDynamicSharedMemorySize,
                             MLP_SMEM);
        k_mlp<<<GRID_MLP, 256, MLP_SMEM>>>((const uint4*)aggh,
                                           Wh, bh, Wo, bo, (float4*)out);
    }
}

// round 17
// speedup vs baseline: 2.4390x; 1.0375x over previous
#include <cuda_runtime.h>
#include <cuda_fp16.h>

#define N_NODES 100000
#define N_EDGES 1000000
#define D_FEAT  64

#define N_TILES   782                 // ceil(N_NODES / 128)
#define GRID_MLP  592                 // 148 SMs x 4 CTAs, persistent

// g_xh:   fp16 copy of X (read-only source for the scatter).
// g_aggh: fp16 accumulator, pre-seeded with fp16(X) by k_init every call, so
//         after the scatter it holds fp16(X[v] + sum_nbr X[u]). k_init
//         overwrites it each call -> graph-replay deterministic, no zeroing.
__device__ __half g_xh[N_NODES * D_FEAT];
__device__ __half g_aggh[N_NODES * D_FEAT];

// ---------------------------------------------------------------------------
// k_init: X (fp32) -> g_xh AND g_aggh (fp16). 25.6MB read + 2x12.8MB write.
// ---------------------------------------------------------------------------
__global__ void k_init(const float4* __restrict__ X4,
                       uint4* __restrict__ xh4, uint4* __restrict__ aggh4,
                       int n) {
    int i = blockIdx.x * blockDim.x + threadIdx.x;   // n = N_NODES*8 uint4
    if (i >= n) return;
    float4 a = __ldg(&X4[2 * i]);
    float4 b = __ldg(&X4[2 * i + 1]);
    __half2 h0 = __floats2half2_rn(a.x, a.y);
    __half2 h1 = __floats2half2_rn(a.z, a.w);
    __half2 h2v = __floats2half2_rn(b.x, b.y);
    __half2 h3 = __floats2half2_rn(b.z, b.w);
    uint4 v = make_uint4(*(unsigned*)&h0, *(unsigned*)&h1,
                         *(unsigned*)&h2v, *(unsigned*)&h3);
    xh4[i] = v;
    aggh4[i] = v;
}

// ---------------------------------------------------------------------------
// Edge scatter: 8 threads per edge; each thread reads 8 fp16 columns (one
// LDG.128 from g_xh, no conversion) and issues one red.v4.f16x2 per direction.
// 16M lane-REDs total — at the halved RED-op floor measured in round 15.
// ---------------------------------------------------------------------------
__device__ __forceinline__ void red16(__half* addr, uint4 h) {
    asm volatile("red.global.add.noftz.v4.f16x2 [%0], {%1, %2, %3, %4};"
                 :: "l"(addr), "r"(h.x), "r"(h.y), "r"(h.z), "r"(h.w)
                 : "memory");
}

__global__ void k_scatter(const uint4* __restrict__ Xh4,
                          const int* __restrict__ ref_a,
                          const int* __restrict__ ref_b) {
    unsigned t = blockIdx.x * blockDim.x + threadIdx.x;
    unsigned e = t >> 3;
    unsigned c = t & 7;          // 8 chunks of 8 fp16 columns (16B each)
    if (e >= N_EDGES) return;
    int a = __ldg(&ref_a[e]);
    int b = __ldg(&ref_b[e]);
    uint4 hb = __ldg(&Xh4[(size_t)b * 8 + c]);
    uint4 ha = __ldg(&Xh4[(size_t)a * 8 + c]);
    red16(&g_aggh[(size_t)a * 64 + 8 * c], hb);
    red16(&g_aggh[(size_t)b * 64 + 8 * c], ha);
}

// ---------------------------------------------------------------------------
// Persistent FP16 m16n8k16 register-fragment MLP (fp32 accumulate):
//   out = relu(relu(agg @ Wh + bh) @ Wo + bo),  agg = fp16(X + sum_nbr X)
// Round-16 structure with bias fragments moved to smem (frees ~32 regs) and
// 4 CTAs/SM (__launch_bounds__(256,4), grid 592) for +33% warps/SM on an
// issue-starved kernel. Pure-copy ingress; warp-private Ts stripes;
// k-permuted fragments; layer-1 accumulators chain directly into layer 2.
// ---------------------------------------------------------------------------
#define TSW 72                                  // Ts row stride in 32-bit words
// Wp 16KB + Bp 512B + Ts 36.9KB = 53.3KB; x4 CTAs = 213KB <= 228KB
#define MLP_SMEM ((4096 + 128 + 128 * TSW) * 4)

__device__ __forceinline__ unsigned h2(float lo, float hi) {
    __half2 h = __floats2half2_rn(lo, hi);
    return *(unsigned*)&h;
}

__device__ __forceinline__ void mma_f16(float* d, unsigned a0, unsigned a1,
                                        unsigned a2, unsigned a3,
                                        unsigned b0, unsigned b1) {
    asm volatile(
        "mma.sync.aligned.m16n8k16.row.col.f32.f16.f16.f32 "
        "{%0,%1,%2,%3}, {%4,%5,%6,%7}, {%8,%9}, {%0,%1,%2,%3};\n"
        : "+f"(d[0]), "+f"(d[1]), "+f"(d[2]), "+f"(d[3])
        : "r"(a0), "r"(a1), "r"(a2), "r"(a3), "r"(b0), "r"(b1));
}

__global__ __launch_bounds__(256, 4)
void k_mlp(const uint4* __restrict__ aggh4,
           const float* __restrict__ Wh_g, const float* __restrict__ bh,
           const float* __restrict__ Wo_g, const float* __restrict__ bo,
           float4* __restrict__ out4) {
    extern __shared__ unsigned sm[];
    unsigned* Wp = sm;                    // [2][2048] packed fp16 weights
    float2*   Bp = (float2*)(sm + 4096);  // [2][8][4] bias (lo,hi) fp32
    unsigned* Ts = sm + 4096 + 128;       // [128][TSW] warp-private staging

    const int tid  = threadIdx.x;
    const int lane = tid & 31;
    const int warp = tid >> 5;
    const int g    = lane >> 2;      // 0..7
    const int tg   = lane & 3;       // 0..3

    // ---- Stage weights ONCE: slot (l, s, np, lane), 4 words per slot ----
    #pragma unroll
    for (int l = 0; l < 2; l++) {
        const float* W = l ? Wo_g : Wh_g;
        #pragma unroll
        for (int ii = 0; ii < 2; ii++) {
            int i = tid + ii * 256;          // 0..511 slots
            int ln = i & 31;
            int np = (i >> 5) & 3;
            int s  = i >> 7;                 // 0..3
            int tgg = ln & 3, gg = ln >> 2;
            int n0 = 16 * np + gg;
            int n1 = n0 + 8;
            unsigned* dst = &Wp[l * 2048 + i * 4];
            if (l == 0) {
                int r = 16 * tgg + 4 * s;
                dst[0] = h2(__ldg(&W[r * 64 + n0]),       __ldg(&W[(r + 1) * 64 + n0]));
                dst[1] = h2(__ldg(&W[(r + 2) * 64 + n0]), __ldg(&W[(r + 3) * 64 + n0]));
                dst[2] = h2(__ldg(&W[r * 64 + n1]),       __ldg(&W[(r + 1) * 64 + n1]));
                dst[3] = h2(__ldg(&W[(r + 2) * 64 + n1]), __ldg(&W[(r + 3) * 64 + n1]));
            } else {
                int ra = 16 * s + 2 * tgg;
                int rb = ra + 8;
                dst[0] = h2(__ldg(&W[ra * 64 + n0]), __ldg(&W[(ra + 1) * 64 + n0]));
                dst[1] = h2(__ldg(&W[rb * 64 + n0]), __ldg(&W[(rb + 1) * 64 + n0]));
                dst[2] = h2(__ldg(&W[ra * 64 + n1]), __ldg(&W[(ra + 1) * 64 + n1]));
                dst[3] = h2(__ldg(&W[rb * 64 + n1]), __ldg(&W[(rb + 1) * 64 + n1]));
            }
        }
    }
    // ---- Stage bias fragments in smem (fp32-exact): [l][nt][tg] ----
    if (tid < 64) {
        int l   = tid >> 5;
        int nt  = (tid >> 2) & 7;
        int tgg = tid & 3;
        const float* B = l ? bo : bh;
        Bp[tid] = make_float2(__ldg(&B[nt * 8 + 2 * tgg]),
                              __ldg(&B[nt * 8 + 2 * tgg + 1]));
    }
    __syncthreads();   // the only block barrier

    const int lr0 = warp * 16 + g;
    const int lr1 = lr0 + 8;

    // ================= Persistent tile loop =================
    for (int tile = blockIdx.x; tile < N_TILES; tile += GRID_MLP) {
        const int row0 = tile * 128;

        // ---- Ingress: pure copy of own 16 fp16 rows (4x LDG.128->STS.128) --
        #pragma unroll
        for (int i = 0; i < 4; i++) {
            int idx = i * 32 + lane;             // 0..127 uint4 in warp tile
            int r  = warp * 16 + (idx >> 3);     // local row (warp-private)
            int c8 = idx & 7;                    // 8-col chunk (uint4)
            int grow = row0 + r;
            uint4 v = make_uint4(0u, 0u, 0u, 0u);
            if (grow < N_NODES) v = __ldg(&aggh4[(size_t)grow * 8 + c8]);
            *(uint4*)&Ts[r * TSW + c8 * 4] = v;
        }
        __syncwarp();

        // ---- Pull A fragments: words [8tg, 8tg+8) of own two rows ----
        unsigned w0[8], w1[8];       // [m] = phys cols (16tg+2m, 16tg+2m+1)
        *(uint4*)&w0[0] = *(const uint4*)&Ts[lr0 * TSW + 8 * tg];
        *(uint4*)&w0[4] = *(const uint4*)&Ts[lr0 * TSW + 8 * tg + 4];
        *(uint4*)&w1[0] = *(const uint4*)&Ts[lr1 * TSW + 8 * tg];
        *(uint4*)&w1[4] = *(const uint4*)&Ts[lr1 * TSW + 8 * tg + 4];

        // ================= Layer 1 =================
        float acc[8][4];
        #pragma unroll
        for (int nt = 0; nt < 8; nt++) {
            float2 b = Bp[nt * 4 + tg];
            acc[nt][0] = b.x; acc[nt][1] = b.y;
            acc[nt][2] = b.x; acc[nt][3] = b.y;
        }
        #pragma unroll
        for (int s = 0; s < 4; s++) {
            unsigned A0 = w0[2 * s],     A1 = w1[2 * s];
            unsigned A2 = w0[2 * s + 1], A3 = w1[2 * s + 1];
            #pragma unroll
            for (int np = 0; np < 4; np++) {
                uint4 b = *(const uint4*)&Wp[((s * 4 + np) * 32 + lane) * 4];
                mma_f16(acc[2 * np],     A0, A1, A2, A3, b.x, b.y);
                mma_f16(acc[2 * np + 1], A0, A1, A2, A3, b.z, b.w);
            }
        }

        // ---- relu + pack: accumulators become layer-2 A fragments ----
        unsigned ha0[4], ha1[4], ha2[4], ha3[4];
        #pragma unroll
        for (int s = 0; s < 4; s++) {
            ha0[s] = h2(fmaxf(acc[2 * s][0], 0.f),     fmaxf(acc[2 * s][1], 0.f));
            ha1[s] = h2(fmaxf(acc[2 * s][2], 0.f),     fmaxf(acc[2 * s][3], 0.f));
            ha2[s] = h2(fmaxf(acc[2 * s + 1][0], 0.f), fmaxf(acc[2 * s + 1][1], 0.f));
            ha3[s] = h2(fmaxf(acc[2 * s + 1][2], 0.f), fmaxf(acc[2 * s + 1][3], 0.f));
        }

        // ================= Layer 2 =================
        #pragma unroll
        for (int nt = 0; nt < 8; nt++) {
            float2 b = Bp[32 + nt * 4 + tg];
            acc[nt][0] = b.x; acc[nt][1] = b.y;
            acc[nt][2] = b.x; acc[nt][3] = b.y;
        }
        #pragma unroll
        for (int s = 0; s < 4; s++) {
            #pragma unroll
            for (int np = 0; np < 4; np++) {
                uint4 b = *(const uint4*)&Wp[2048 + ((s * 4 + np) * 32 + lane) * 4];
                mma_f16(acc[2 * np],     ha0[s], ha1[s], ha2[s], ha3[s], b.x, b.y);
                mma_f16(acc[2 * np + 1], ha0[s], ha1[s], ha2[s], ha3[s], b.z, b.w);
            }
        }

        // ---- Egress: relu -> own warp stripe as fp32 (warp-private) ----
        __syncwarp();
        #pragma unroll
        for (int nt = 0; nt < 8; nt++) {
            int c = nt * 8 + 2 * tg;
            *(uint2*)&Ts[lr0 * TSW + c] = make_uint2(
                __float_as_uint(fmaxf(acc[nt][0], 0.f)),
                __float_as_uint(fmaxf(acc[nt][1], 0.f)));
            *(uint2*)&Ts[lr1 * TSW + c] = make_uint2(
                __float_as_uint(fmaxf(acc[nt][2], 0.f)),
                __float_as_uint(fmaxf(acc[nt][3], 0.f)));
        }
        __syncwarp();

        // ---- Per-warp coalesced STG.128 of own 16 output rows ----
        #pragma unroll
        for (int i = 0; i < 8; i++) {
            int idx = i * 32 + lane;
            int r  = warp * 16 + (idx >> 4);
            int c4 = idx & 15;
            int grow = row0 + r;
            if (grow < N_NODES) {
                uint4 v = *(const uint4*)&Ts[r * TSW + c4 * 4];
                out4[(size_t)grow * 16 + c4] = make_float4(
                    __uint_as_float(v.x), __uint_as_float(v.y),
                    __uint_as_float(v.z), __uint_as_float(v.w));
            }
        }
        __syncwarp();   // stripe reuse guard before next tile's ingress
    }
}

// ---------------------------------------------------------------------------
// Inputs: 0=X, 1=ref_a, 2=ref_b, 3=v_map(unused), 4=v_count(unused),
//         5=W_hidden, 6=b_hidden, 7=W_out, 8=b_out
// ---------------------------------------------------------------------------
extern "C" void kernel_launch(void* const* d_in, const int* in_sizes, int n_in,
                              void* d_out, int out_size) {
    const float* X   = (const float*)d_in[0];
    const int* ref_a = (const int*)d_in[1];
    const int* ref_b = (const int*)d_in[2];
    const float* Wh  = (const float*)d_in[5];
    const float* bh  = (const float*)d_in[6];
    const float* Wo  = (const float*)d_in[7];
    const float* bo  = (const float*)d_in[8];
    float* out = (float*)d_out;

    __half* xh;
    cudaGetSymbolAddress((void**)&xh, g_xh);
    __half* aggh;
    cudaGetSymbolAddress((void**)&aggh, g_aggh);

    // 1) fp16 X copy + accumulator pre-seeded with the self term
    {
        int n = N_NODES * D_FEAT / 8;    // 800k uint4
        k_init<<<(n + 255) / 256, 256>>>((const float4*)X, (uint4*)xh,
                                         (uint4*)aggh, n);
    }

    // 2) edge scatter: fp16 reads, f16x2 REDs (no conversion anywhere)
    {
        long long total = (long long)N_EDGES * 8;
        int blocks = (int)((total + 255) / 256);
        k_scatter<<<blocks, 256>>>((const uint4*)xh, ref_a, ref_b);
    }

    // 3) persistent FP16 MLP, 4 CTAs/SM
    {
        cudaFuncSetAttribute(k_mlp, cudaFuncAttributeMaxDynamicSharedMemorySize,
                             MLP_SMEM);
        k_mlp<<<GRID_MLP, 256, MLP_SMEM>>>((const uint4*)aggh,
                                           Wh, bh, Wo, bo, (float4*)out);
    }
}